// round 1
// baseline (speedup 1.0000x reference)
#include <cuda_runtime.h>
#include <math.h>
#include <stdint.h>

#define B_    16
#define C_    256
#define N_    1024      // 32*32 tokens
#define NH_   8
#define HD_   32
#define HALF_ 128
#define BH_   (B_*NH_)  // 128
#define TABN_ 3969      // 63*63

// ---- scratch (device globals; no runtime allocation allowed) ----
__device__ float g_q[BH_*N_*HD_];      // 16 MB (normalized in-place)
__device__ float g_k[BH_*N_*HD_];      // 16 MB
__device__ float g_v[BH_*N_*HD_];      // 16 MB
__device__ float g_o[BH_*N_*HD_];      // 16 MB
__device__ float g_tab[TABN_*NH_];     // 127 KB
__device__ float g_biasT[NH_*N_*N_];   // 32 MB, layout [h][m][n]

// ============================================================
// K0: QKV projection with residual. x:(b,c,32,32) -> q,k,v [bh][n][d]
// 16 tokens per block, 256 threads. Warp-level mapping keeps shared
// weight reads broadcast and global reads coalesced.
// ============================================================
__global__ void __launch_bounds__(256) qkv_kernel(
    const float* __restrict__ x,
    const float* __restrict__ q1w, const float* __restrict__ q1b,
    const float* __restrict__ q2w, const float* __restrict__ q2b,
    const float* __restrict__ k1w, const float* __restrict__ k1b,
    const float* __restrict__ k2w, const float* __restrict__ k2b,
    const float* __restrict__ v1w, const float* __restrict__ v1b,
    const float* __restrict__ v2w, const float* __restrict__ v2b)
{
    __shared__ float x_s[16][C_];      // 16 KB
    __shared__ float w_s[HALF_][32];   // 16 KB, chunk of W: w_s[oc][ii]

    const int tid  = threadIdx.x;
    const int tok0 = blockIdx.x * 16;
    const int b    = tok0 / N_;
    const int n0   = tok0 % N_;

    // stage x for 16 tokens (coalesced over tokens)
    for (int idx = tid; idx < 16 * C_; idx += 256) {
        int c = idx >> 4, t = idx & 15;
        x_s[t][c] = x[(b * C_ + c) * N_ + n0 + t];
    }
    __syncthreads();

    const float* Ws[6] = {q1w, q2w, k1w, k2w, v1w, v2w};
    const float* Bs[6] = {q1b, q2b, k1b, k2b, v1b, v2b};
    float*       Os[6] = {g_q, g_q, g_k, g_k, g_v, g_v};

    const int lane  = tid & 31;
    const int warp  = tid >> 5;              // 0..7
    const int t     = lane & 15;             // token within block
    const int sub   = lane >> 4;             // 0/1
    const int oc0   = warp * 16 + sub * 8;   // 8 consecutive out channels

    for (int m = 0; m < 6; m++) {
        const int half = m & 1;
        const float* W  = Ws[m];
        const float* bb = Bs[m];

        float acc[8];
        #pragma unroll
        for (int u = 0; u < 8; u++)
            acc[u] = x_s[t][half * HALF_ + oc0 + u] + bb[oc0 + u];

        for (int ch = 0; ch < 4; ch++) {
            __syncthreads();
            // load W chunk [128 oc][32 i] row-major (coalesced both sides)
            for (int idx = tid; idx < HALF_ * 32; idx += 256) {
                int oc = idx >> 5, ii = idx & 31;
                w_s[oc][ii] = W[oc * HALF_ + ch * 32 + ii];
            }
            __syncthreads();
            #pragma unroll 8
            for (int ii = 0; ii < 32; ii++) {
                float xv = x_s[t][half * HALF_ + ch * 32 + ii];
                #pragma unroll
                for (int u = 0; u < 8; u++)
                    acc[u] += xv * w_s[oc0 + u][ii];   // 2-way broadcast read
            }
        }

        const int c    = half * HALF_ + oc0;  // within one head (oc0 % 8 == 0)
        const int head = c >> 5, d = c & 31;
        float* out = Os[m] + (((b * NH_ + head) * N_) + (n0 + t)) * HD_ + d;
        *(float4*)(out)     = make_float4(acc[0], acc[1], acc[2], acc[3]);
        *(float4*)(out + 4) = make_float4(acc[4], acc[5], acc[6], acc[7]);
    }
}

// ============================================================
// K1: normalize q and k rows (length 32) in place. 1 thread / row.
// ============================================================
__global__ void __launch_bounds__(256) norm_kernel()
{
    int r = blockIdx.x * 256 + threadIdx.x;     // 0 .. 2*BH*N-1
    float* base = (r < BH_ * N_) ? g_q : g_k;
    int row = (r < BH_ * N_) ? r : r - BH_ * N_;
    float4* p = (float4*)(base + (size_t)row * HD_);
    float4 v[8];
    float s = 0.f;
    #pragma unroll
    for (int u = 0; u < 8; u++) {
        v[u] = p[u];
        s += v[u].x * v[u].x + v[u].y * v[u].y + v[u].z * v[u].z + v[u].w * v[u].w;
    }
    float inv = 1.f / fmaxf(sqrtf(s), 1e-12f);
    #pragma unroll
    for (int u = 0; u < 8; u++) {
        v[u].x *= inv; v[u].y *= inv; v[u].z *= inv; v[u].w *= inv;
        p[u] = v[u];
    }
}

// ============================================================
// K2: CPB table: 63x63 grid -> MLP(2->128 relu ->8) -> g_tab[pos][h]
// ============================================================
__global__ void __launch_bounds__(256) tab_kernel(
    const float* __restrict__ w1, const float* __restrict__ b1,
    const float* __restrict__ w2)
{
    __shared__ float w1s[256];   // [k][2]
    __shared__ float b1s[128];
    __shared__ float w2s[1024];  // [h][k]
    int tid = threadIdx.x;
    if (tid < 256) w1s[tid] = w1[tid];
    if (tid < 128) b1s[tid] = b1[tid];
    for (int i = tid; i < 1024; i += 256) w2s[i] = w2[i];
    __syncthreads();

    int p = blockIdx.x * 256 + tid;
    if (p >= TABN_) return;
    int a = p / 63, b = p % 63;
    float t0 = ((float)(a - 31) / 31.0f) * 3.2f;
    float t1 = ((float)(b - 31) / 31.0f) * 3.2f;
    t0 = copysignf(1.f - __expf(-fabsf(t0)), t0);
    t1 = copysignf(1.f - __expf(-fabsf(t1)), t1);

    float acc[NH_];
    #pragma unroll
    for (int h = 0; h < NH_; h++) acc[h] = 0.f;
    for (int k = 0; k < 128; k++) {
        float hv = fmaxf(w1s[2 * k] * t0 + w1s[2 * k + 1] * t1 + b1s[k], 0.f);
        #pragma unroll
        for (int h = 0; h < NH_; h++) acc[h] += w2s[h * 128 + k] * hv;
    }
    #pragma unroll
    for (int h = 0; h < NH_; h++) g_tab[p * NH_ + h] = acc[h];
}

// ============================================================
// K3: expand bias to [h][m][n] = 16*sigmoid(tab[idx(n,m)][h])
// ============================================================
__global__ void __launch_bounds__(256) bias_kernel()
{
    int m = blockIdx.x;
    int n = blockIdx.y * 256 + threadIdx.x;
    int i = n >> 5, j = n & 31;
    int p = m >> 5, q = m & 31;
    int idx = (i - p + 31) * 63 + (j - q + 31);
    const float* t = g_tab + idx * NH_;
    #pragma unroll
    for (int h = 0; h < NH_; h++) {
        float v = 16.f / (1.f + __expf(-t[h]));
        g_biasT[((size_t)h * N_ + m) * N_ + n] = v;
    }
}

// ============================================================
// K4: attention. grid (8 qtiles, 128 bh), 128 threads, 1 query/thread.
// Streaming softmax with per-head constant shift M = scale + 16
// (score = s*scale + bias <= scale + 16, so exp arg <= 0; min arg is
//  -2*scale-16 = -36 here -> no over/underflow, sum > 0).
// ============================================================
__global__ void __launch_bounds__(128) attn_kernel(const float* __restrict__ logit_scale)
{
    const int MT = 32;
    __shared__ float4 k_s[MT * 8];        // 4 KB
    __shared__ float4 v_s[MT * 8];        // 4 KB
    __shared__ float  bias_s[MT][128];    // 16 KB

    const int tid = threadIdx.x;
    const int bh  = blockIdx.y;
    const int h   = bh & 7;
    const int n   = blockIdx.x * 128 + tid;

    const float4* qp = (const float4*)(g_q + ((size_t)bh * N_ + n) * HD_);
    float4 q4[8];
    #pragma unroll
    for (int u = 0; u < 8; u++) q4[u] = qp[u];

    const float scale = __expf(fminf(logit_scale[h], 4.6051702f)); // log(100)
    const float M = scale + 16.0f;

    float4 o4[8];
    #pragma unroll
    for (int u = 0; u < 8; u++) o4[u] = make_float4(0.f, 0.f, 0.f, 0.f);
    float sum = 0.f;

    const float4* kbase = (const float4*)(g_k + (size_t)bh * N_ * HD_);
    const float4* vbase = (const float4*)(g_v + (size_t)bh * N_ * HD_);
    const float*  bbase = g_biasT + (size_t)h * N_ * N_ + blockIdx.x * 128;

    for (int m0 = 0; m0 < N_; m0 += MT) {
        __syncthreads();
        #pragma unroll
        for (int u = 0; u < 2; u++) {
            k_s[u * 128 + tid] = kbase[m0 * 8 + u * 128 + tid];
            v_s[u * 128 + tid] = vbase[m0 * 8 + u * 128 + tid];
        }
        #pragma unroll
        for (int u = 0; u < 8; u++) {
            int lin = u * 128 + tid;              // 0..1023 float4s
            int mm = lin >> 5, nn4 = lin & 31;
            ((float4*)bias_s)[lin] =
                *(const float4*)(bbase + (size_t)(m0 + mm) * N_ + nn4 * 4);
        }
        __syncthreads();

        #pragma unroll 4
        for (int j = 0; j < MT; j++) {
            float s = 0.f;
            #pragma unroll
            for (int u = 0; u < 8; u++) {
                float4 kk = k_s[j * 8 + u];
                s += q4[u].x * kk.x + q4[u].y * kk.y + q4[u].z * kk.z + q4[u].w * kk.w;
            }
            float pr = __expf(s * scale + bias_s[j][tid] - M);
            sum += pr;
            #pragma unroll
            for (int u = 0; u < 8; u++) {
                float4 vv = v_s[j * 8 + u];
                o4[u].x += pr * vv.x; o4[u].y += pr * vv.y;
                o4[u].z += pr * vv.z; o4[u].w += pr * vv.w;
            }
        }
    }

    float inv = 1.f / sum;
    float4* op = (float4*)(g_o + ((size_t)bh * N_ + n) * HD_);
    #pragma unroll
    for (int u = 0; u < 8; u++) {
        o4[u].x *= inv; o4[u].y *= inv; o4[u].z *= inv; o4[u].w *= inv;
        op[u] = o4[u];
    }
}

// ============================================================
// K5: output projection, write NCHW output.
// ============================================================
__global__ void __launch_bounds__(256) proj_kernel(
    const float* __restrict__ p1w, const float* __restrict__ p1b,
    const float* __restrict__ p2w, const float* __restrict__ p2b,
    float* __restrict__ out)
{
    __shared__ float o_s[16][C_];      // 16 KB
    __shared__ float w_s[HALF_][16];   // 8 KB chunk
    __shared__ float y_s[16][C_];      // 16 KB

    const int tid  = threadIdx.x;
    const int tok0 = blockIdx.x * 16;
    const int b    = tok0 / N_;
    const int n0   = tok0 % N_;

    // stage attention output tokens: o_s[t][c]
    for (int idx = tid; idx < 16 * C_; idx += 256) {
        int t = idx >> 8, c = idx & 255;
        o_s[t][c] = g_o[(((size_t)b * NH_ + (c >> 5)) * N_ + n0 + t) * HD_ + (c & 31)];
    }
    __syncthreads();

    const float* Ws[2] = {p1w, p2w};
    const float* Bs[2] = {p1b, p2b};

    const int lane = tid & 31;
    const int warp = tid >> 5;
    const int t    = lane & 15;
    const int sub  = lane >> 4;
    const int oc0  = warp * 16 + sub * 8;

    for (int m = 0; m < 2; m++) {
        const int half = m;
        const float* W  = Ws[m];
        const float* bb = Bs[m];
        float acc[8];
        #pragma unroll
        for (int u = 0; u < 8; u++) acc[u] = bb[oc0 + u];

        for (int ch = 0; ch < 8; ch++) {
            __syncthreads();
            for (int idx = tid; idx < HALF_ * 16; idx += 256) {
                int oc = idx >> 4, ii = idx & 15;
                w_s[oc][ii] = W[oc * HALF_ + ch * 16 + ii];
            }
            __syncthreads();
            #pragma unroll 8
            for (int ii = 0; ii < 16; ii++) {
                float xv = o_s[t][half * HALF_ + ch * 16 + ii];
                #pragma unroll
                for (int u = 0; u < 8; u++)
                    acc[u] += xv * w_s[oc0 + u][ii];
            }
        }
        #pragma unroll
        for (int u = 0; u < 8; u++) y_s[t][half * HALF_ + oc0 + u] = acc[u];
    }
    __syncthreads();

    // write NCHW (coalesced over tokens)
    for (int idx = tid; idx < 16 * C_; idx += 256) {
        int c = idx >> 4, t2 = idx & 15;
        out[((size_t)b * C_ + c) * N_ + n0 + t2] = y_s[t2][c];
    }
}

// ============================================================
extern "C" void kernel_launch(void* const* d_in, const int* in_sizes, int n_in,
                              void* d_out, int out_size)
{
    const float* x    = (const float*)d_in[0];
    const float* q1w  = (const float*)d_in[1];
    const float* q1b  = (const float*)d_in[2];
    const float* q2w  = (const float*)d_in[3];
    const float* q2b  = (const float*)d_in[4];
    const float* k1w  = (const float*)d_in[5];
    const float* k1b  = (const float*)d_in[6];
    const float* k2w  = (const float*)d_in[7];
    const float* k2b  = (const float*)d_in[8];
    const float* v1w  = (const float*)d_in[9];
    const float* v1b  = (const float*)d_in[10];
    const float* v2w  = (const float*)d_in[11];
    const float* v2b  = (const float*)d_in[12];
    const float* p1w  = (const float*)d_in[13];
    const float* p1b  = (const float*)d_in[14];
    const float* p2w  = (const float*)d_in[15];
    const float* p2b  = (const float*)d_in[16];
    const float* ls   = (const float*)d_in[17];
    const float* m1w  = (const float*)d_in[18];
    const float* m1b  = (const float*)d_in[19];
    const float* m2w  = (const float*)d_in[20];
    float* out = (float*)d_out;

    qkv_kernel<<<B_ * N_ / 16, 256>>>(x, q1w, q1b, q2w, q2b,
                                      k1w, k1b, k2w, k2b,
                                      v1w, v1b, v2w, v2b);
    norm_kernel<<<2 * BH_ * N_ / 256, 256>>>();
    tab_kernel<<<(TABN_ + 255) / 256, 256>>>(m1w, m1b, m2w);
    bias_kernel<<<dim3(N_, N_ / 256), 256>>>();
    attn_kernel<<<dim3(N_ / 128, BH_), 128>>>(ls);
    proj_kernel<<<B_ * N_ / 16, 256>>>(p1w, p1b, p2w, p2b, out);
}

// round 2
// speedup vs baseline: 1.0787x; 1.0787x over previous
#include <cuda_runtime.h>
#include <math.h>
#include <stdint.h>

#define B_    16
#define C_    256
#define N_    1024      // 32*32 tokens
#define NH_   8
#define HD_   32
#define HALF_ 128
#define BH_   (B_*NH_)  // 128
#define TABN_ 3969      // 63*63

typedef unsigned long long u64;

// packed fp32x2 ops (sm_100+; ptxas never auto-generates these)
#define FMA2(d,a,b,c) asm("fma.rn.f32x2 %0, %1, %2, %3;" : "=l"(d) : "l"(a), "l"(b), "l"(c))
#define MUL2(d,a,b)   asm("mul.rn.f32x2 %0, %1, %2;"     : "=l"(d) : "l"(a), "l"(b))
#define PACK2(d,x)    asm("mov.b64 %0, {%1, %1};"        : "=l"(d) : "f"(x))
#define UNPACK2(lo,hi,p) asm("mov.b64 {%0, %1}, %2;" : "=f"(lo), "=f"(hi) : "l"(p))

// ---- scratch (device globals; no runtime allocation allowed) ----
__device__ float g_q[BH_*N_*HD_];      // 16 MB (normalized in-place)
__device__ float g_k[BH_*N_*HD_];      // 16 MB
__device__ float g_v[BH_*N_*HD_];      // 16 MB
__device__ float g_o[BH_*N_*HD_];      // 16 MB
__device__ float g_tab[TABN_*NH_];     // 127 KB
__device__ float g_biasT[NH_*N_*N_];   // 32 MB, layout [h][m][n]

// ============================================================
// K0: QKV projection with residual. x:(b,c,32,32) -> q,k,v [bh][n][d]
// ============================================================
__global__ void __launch_bounds__(256) qkv_kernel(
    const float* __restrict__ x,
    const float* __restrict__ q1w, const float* __restrict__ q1b,
    const float* __restrict__ q2w, const float* __restrict__ q2b,
    const float* __restrict__ k1w, const float* __restrict__ k1b,
    const float* __restrict__ k2w, const float* __restrict__ k2b,
    const float* __restrict__ v1w, const float* __restrict__ v1b,
    const float* __restrict__ v2w, const float* __restrict__ v2b)
{
    __shared__ float x_s[16][C_];      // 16 KB
    __shared__ float w_s[HALF_][32];   // 16 KB

    const int tid  = threadIdx.x;
    const int tok0 = blockIdx.x * 16;
    const int b    = tok0 / N_;
    const int n0   = tok0 % N_;

    for (int idx = tid; idx < 16 * C_; idx += 256) {
        int c = idx >> 4, t = idx & 15;
        x_s[t][c] = x[(b * C_ + c) * N_ + n0 + t];
    }
    __syncthreads();

    const float* Ws[6] = {q1w, q2w, k1w, k2w, v1w, v2w};
    const float* Bs[6] = {q1b, q2b, k1b, k2b, v1b, v2b};
    float*       Os[6] = {g_q, g_q, g_k, g_k, g_v, g_v};

    const int lane  = tid & 31;
    const int warp  = tid >> 5;
    const int t     = lane & 15;
    const int sub   = lane >> 4;
    const int oc0   = warp * 16 + sub * 8;

    for (int m = 0; m < 6; m++) {
        const int half = m & 1;
        const float* W  = Ws[m];
        const float* bb = Bs[m];

        float acc[8];
        #pragma unroll
        for (int u = 0; u < 8; u++)
            acc[u] = x_s[t][half * HALF_ + oc0 + u] + bb[oc0 + u];

        for (int ch = 0; ch < 4; ch++) {
            __syncthreads();
            for (int idx = tid; idx < HALF_ * 32; idx += 256) {
                int oc = idx >> 5, ii = idx & 31;
                w_s[oc][ii] = W[oc * HALF_ + ch * 32 + ii];
            }
            __syncthreads();
            #pragma unroll 8
            for (int ii = 0; ii < 32; ii++) {
                float xv = x_s[t][half * HALF_ + ch * 32 + ii];
                #pragma unroll
                for (int u = 0; u < 8; u++)
                    acc[u] += xv * w_s[oc0 + u][ii];
            }
        }

        const int c    = half * HALF_ + oc0;
        const int head = c >> 5, d = c & 31;
        float* out = Os[m] + (((b * NH_ + head) * N_) + (n0 + t)) * HD_ + d;
        *(float4*)(out)     = make_float4(acc[0], acc[1], acc[2], acc[3]);
        *(float4*)(out + 4) = make_float4(acc[4], acc[5], acc[6], acc[7]);
    }
}

// ============================================================
// K1: normalize q and k rows (length 32) in place.
// ============================================================
__global__ void __launch_bounds__(256) norm_kernel()
{
    int r = blockIdx.x * 256 + threadIdx.x;
    float* base = (r < BH_ * N_) ? g_q : g_k;
    int row = (r < BH_ * N_) ? r : r - BH_ * N_;
    float4* p = (float4*)(base + (size_t)row * HD_);
    float4 v[8];
    float s = 0.f;
    #pragma unroll
    for (int u = 0; u < 8; u++) {
        v[u] = p[u];
        s += v[u].x * v[u].x + v[u].y * v[u].y + v[u].z * v[u].z + v[u].w * v[u].w;
    }
    float inv = 1.f / fmaxf(sqrtf(s), 1e-12f);
    #pragma unroll
    for (int u = 0; u < 8; u++) {
        v[u].x *= inv; v[u].y *= inv; v[u].z *= inv; v[u].w *= inv;
        p[u] = v[u];
    }
}

// ============================================================
// K2: CPB table MLP
// ============================================================
__global__ void __launch_bounds__(256) tab_kernel(
    const float* __restrict__ w1, const float* __restrict__ b1,
    const float* __restrict__ w2)
{
    __shared__ float w1s[256];
    __shared__ float b1s[128];
    __shared__ float w2s[1024];
    int tid = threadIdx.x;
    if (tid < 256) w1s[tid] = w1[tid];
    if (tid < 128) b1s[tid] = b1[tid];
    for (int i = tid; i < 1024; i += 256) w2s[i] = w2[i];
    __syncthreads();

    int p = blockIdx.x * 256 + tid;
    if (p >= TABN_) return;
    int a = p / 63, b = p % 63;
    float t0 = ((float)(a - 31) / 31.0f) * 3.2f;
    float t1 = ((float)(b - 31) / 31.0f) * 3.2f;
    t0 = copysignf(1.f - __expf(-fabsf(t0)), t0);
    t1 = copysignf(1.f - __expf(-fabsf(t1)), t1);

    float acc[NH_];
    #pragma unroll
    for (int h = 0; h < NH_; h++) acc[h] = 0.f;
    for (int k = 0; k < 128; k++) {
        float hv = fmaxf(w1s[2 * k] * t0 + w1s[2 * k + 1] * t1 + b1s[k], 0.f);
        #pragma unroll
        for (int h = 0; h < NH_; h++) acc[h] += w2s[h * 128 + k] * hv;
    }
    #pragma unroll
    for (int h = 0; h < NH_; h++) g_tab[p * NH_ + h] = acc[h];
}

// ============================================================
// K3: expand bias to [h][m][n]
// ============================================================
__global__ void __launch_bounds__(256) bias_kernel()
{
    int m = blockIdx.x;
    int n = blockIdx.y * 256 + threadIdx.x;
    int i = n >> 5, j = n & 31;
    int p = m >> 5, q = m & 31;
    int idx = (i - p + 31) * 63 + (j - q + 31);
    const float* t = g_tab + idx * NH_;
    #pragma unroll
    for (int h = 0; h < NH_; h++) {
        float v = 16.f / (1.f + __expf(-t[h]));
        g_biasT[((size_t)h * N_ + m) * N_ + n] = v;
    }
}

// ============================================================
// K4: attention, fp32x2 packed math, 2 queries per thread.
// grid (N/256, BH), 128 threads. Streaming softmax with constant
// shift M = scale + 16 (exp arg in [-2*scale-16, 0]).
// ============================================================
__global__ void __launch_bounds__(128, 3) attn_kernel(const float* __restrict__ logit_scale)
{
    const int MT = 32;                       // keys per tile
    __shared__ ulonglong2 k_s[MT * 8];       // 32 keys x 32 f32 = 4 KB
    __shared__ ulonglong2 v_s[MT * 8];       // 4 KB
    __shared__ float bias_s[MT][256];        // 32 KB

    const int tid = threadIdx.x;
    const int bh  = blockIdx.y;
    const int h   = bh & 7;
    const int q0  = blockIdx.x * 256 + tid * 2;   // two adjacent queries

    // q rows for both queries, packed as f32x2 (8 x ulonglong2 each)
    u64 qa[16], qb[16];
    {
        const ulonglong2* qpa = (const ulonglong2*)(g_q + ((size_t)bh * N_ + q0) * HD_);
        #pragma unroll
        for (int u = 0; u < 8; u++) {
            ulonglong2 t0 = qpa[u];     qa[2*u] = t0.x; qa[2*u+1] = t0.y;
            ulonglong2 t1 = qpa[u + 8]; qb[2*u] = t1.x; qb[2*u+1] = t1.y;
        }
    }

    const float scale = __expf(fminf(logit_scale[h], 4.6051702f)); // log(100)
    const float M = scale + 16.0f;

    u64 oa[16], ob[16];
    #pragma unroll
    for (int u = 0; u < 16; u++) { oa[u] = 0ull; ob[u] = 0ull; }
    float suma = 0.f, sumb = 0.f;

    const ulonglong2* kbase = (const ulonglong2*)(g_k + (size_t)bh * N_ * HD_);
    const ulonglong2* vbase = (const ulonglong2*)(g_v + (size_t)bh * N_ * HD_);
    const float*      bbase = g_biasT + (size_t)h * N_ * N_ + blockIdx.x * 256;

    for (int m0 = 0; m0 < N_; m0 += MT) {
        __syncthreads();
        // stage K/V tile: 32 keys x 8 ulonglong2 = 256 each, 128 threads -> 2 apiece
        #pragma unroll
        for (int u = 0; u < 2; u++) {
            k_s[u * 128 + tid] = kbase[m0 * 8 + u * 128 + tid];
            v_s[u * 128 + tid] = vbase[m0 * 8 + u * 128 + tid];
        }
        // stage bias tile [32 keys][256 queries] = 2048 float4
        #pragma unroll
        for (int u = 0; u < 16; u++) {
            int idx = u * 128 + tid;             // 0..2047
            int mm = idx >> 6, nn = idx & 63;
            ((float4*)bias_s)[idx] =
                *(const float4*)(bbase + (size_t)(m0 + mm) * N_ + nn * 4);
        }
        __syncthreads();

        #pragma unroll 2
        for (int j = 0; j < MT; j++) {
            // QK dots for both queries, 2 chains each for ILP
            u64 sa0 = 0ull, sa1 = 0ull, sb0 = 0ull, sb1 = 0ull;
            const ulonglong2* kk = &k_s[j * 8];
            #pragma unroll
            for (int u = 0; u < 4; u++) {
                ulonglong2 k0 = kk[2*u];
                ulonglong2 k1 = kk[2*u+1];
                FMA2(sa0, qa[4*u+0], k0.x, sa0);
                FMA2(sa1, qa[4*u+1], k0.y, sa1);
                FMA2(sb0, qb[4*u+0], k0.x, sb0);
                FMA2(sb1, qb[4*u+1], k0.y, sb1);
                FMA2(sa0, qa[4*u+2], k1.x, sa0);
                FMA2(sa1, qa[4*u+3], k1.y, sa1);
                FMA2(sb0, qb[4*u+2], k1.x, sb0);
                FMA2(sb1, qb[4*u+3], k1.y, sb1);
            }
            float a0l, a0h, a1l, a1h, b0l, b0h, b1l, b1h;
            UNPACK2(a0l, a0h, sa0); UNPACK2(a1l, a1h, sa1);
            UNPACK2(b0l, b0h, sb0); UNPACK2(b1l, b1h, sb1);
            float s_a = (a0l + a0h) + (a1l + a1h);
            float s_b = (b0l + b0h) + (b1l + b1h);

            float2 bij = *(const float2*)&bias_s[j][tid * 2];
            float pa = __expf(fmaf(s_a, scale, bij.x - M));
            float pb = __expf(fmaf(s_b, scale, bij.y - M));
            suma += pa; sumb += pb;

            u64 pa2, pb2;
            PACK2(pa2, pa); PACK2(pb2, pb);
            const ulonglong2* vv = &v_s[j * 8];
            #pragma unroll
            for (int u = 0; u < 8; u++) {
                ulonglong2 vj = vv[u];
                FMA2(oa[2*u],   pa2, vj.x, oa[2*u]);
                FMA2(oa[2*u+1], pa2, vj.y, oa[2*u+1]);
                FMA2(ob[2*u],   pb2, vj.x, ob[2*u]);
                FMA2(ob[2*u+1], pb2, vj.y, ob[2*u+1]);
            }
        }
    }

    float inva = 1.f / suma, invb = 1.f / sumb;
    u64 ia, ib; PACK2(ia, inva); PACK2(ib, invb);
    ulonglong2* op = (ulonglong2*)(g_o + ((size_t)bh * N_ + q0) * HD_);
    #pragma unroll
    for (int u = 0; u < 8; u++) {
        ulonglong2 ra, rb;
        MUL2(ra.x, oa[2*u], ia); MUL2(ra.y, oa[2*u+1], ia);
        MUL2(rb.x, ob[2*u], ib); MUL2(rb.y, ob[2*u+1], ib);
        op[u]     = ra;
        op[u + 8] = rb;
    }
}

// ============================================================
// K5: output projection, write NCHW output.
// ============================================================
__global__ void __launch_bounds__(256) proj_kernel(
    const float* __restrict__ p1w, const float* __restrict__ p1b,
    const float* __restrict__ p2w, const float* __restrict__ p2b,
    float* __restrict__ out)
{
    __shared__ float o_s[16][C_];
    __shared__ float w_s[HALF_][16];
    __shared__ float y_s[16][C_];

    const int tid  = threadIdx.x;
    const int tok0 = blockIdx.x * 16;
    const int b    = tok0 / N_;
    const int n0   = tok0 % N_;

    for (int idx = tid; idx < 16 * C_; idx += 256) {
        int t = idx >> 8, c = idx & 255;
        o_s[t][c] = g_o[(((size_t)b * NH_ + (c >> 5)) * N_ + n0 + t) * HD_ + (c & 31)];
    }
    __syncthreads();

    const float* Ws[2] = {p1w, p2w};
    const float* Bs[2] = {p1b, p2b};

    const int lane = tid & 31;
    const int warp = tid >> 5;
    const int t    = lane & 15;
    const int sub  = lane >> 4;
    const int oc0  = warp * 16 + sub * 8;

    for (int m = 0; m < 2; m++) {
        const int half = m;
        const float* W  = Ws[m];
        const float* bb = Bs[m];
        float acc[8];
        #pragma unroll
        for (int u = 0; u < 8; u++) acc[u] = bb[oc0 + u];

        for (int ch = 0; ch < 8; ch++) {
            __syncthreads();
            for (int idx = tid; idx < HALF_ * 16; idx += 256) {
                int oc = idx >> 4, ii = idx & 15;
                w_s[oc][ii] = W[oc * HALF_ + ch * 16 + ii];
            }
            __syncthreads();
            #pragma unroll 8
            for (int ii = 0; ii < 16; ii++) {
                float xv = o_s[t][half * HALF_ + ch * 16 + ii];
                #pragma unroll
                for (int u = 0; u < 8; u++)
                    acc[u] += xv * w_s[oc0 + u][ii];
            }
        }
        #pragma unroll
        for (int u = 0; u < 8; u++) y_s[t][half * HALF_ + oc0 + u] = acc[u];
    }
    __syncthreads();

    for (int idx = tid; idx < 16 * C_; idx += 256) {
        int c = idx >> 4, t2 = idx & 15;
        out[((size_t)b * C_ + c) * N_ + n0 + t2] = y_s[t2][c];
    }
}

// ============================================================
extern "C" void kernel_launch(void* const* d_in, const int* in_sizes, int n_in,
                              void* d_out, int out_size)
{
    const float* x    = (const float*)d_in[0];
    const float* q1w  = (const float*)d_in[1];
    const float* q1b  = (const float*)d_in[2];
    const float* q2w  = (const float*)d_in[3];
    const float* q2b  = (const float*)d_in[4];
    const float* k1w  = (const float*)d_in[5];
    const float* k1b  = (const float*)d_in[6];
    const float* k2w  = (const float*)d_in[7];
    const float* k2b  = (const float*)d_in[8];
    const float* v1w  = (const float*)d_in[9];
    const float* v1b  = (const float*)d_in[10];
    const float* v2w  = (const float*)d_in[11];
    const float* v2b  = (const float*)d_in[12];
    const float* p1w  = (const float*)d_in[13];
    const float* p1b  = (const float*)d_in[14];
    const float* p2w  = (const float*)d_in[15];
    const float* p2b  = (const float*)d_in[16];
    const float* ls   = (const float*)d_in[17];
    const float* m1w  = (const float*)d_in[18];
    const float* m1b  = (const float*)d_in[19];
    const float* m2w  = (const float*)d_in[20];
    float* out = (float*)d_out;

    qkv_kernel<<<B_ * N_ / 16, 256>>>(x, q1w, q1b, q2w, q2b,
                                      k1w, k1b, k2w, k2b,
                                      v1w, v1b, v2w, v2b);
    norm_kernel<<<2 * BH_ * N_ / 256, 256>>>();
    tab_kernel<<<(TABN_ + 255) / 256, 256>>>(m1w, m1b, m2w);
    bias_kernel<<<dim3(N_, N_ / 256), 256>>>();
    attn_kernel<<<dim3(N_ / 256, BH_), 128>>>(ls);
    proj_kernel<<<B_ * N_ / 16, 256>>>(p1w, p1b, p2w, p2b, out);
}

// round 3
// speedup vs baseline: 1.1581x; 1.0736x over previous
#include <cuda_runtime.h>
#include <math.h>
#include <stdint.h>

#define B_    16
#define C_    256
#define N_    1024      // 32*32 tokens
#define NH_   8
#define HD_   32
#define HALF_ 128
#define BH_   (B_*NH_)  // 128
#define TABN_ 3969      // 63*63

typedef unsigned long long u64;

// packed fp32x2 ops (sm_100+; ptxas never auto-generates these)
#define FMA2(d,a,b,c) asm("fma.rn.f32x2 %0, %1, %2, %3;" : "=l"(d) : "l"(a), "l"(b), "l"(c))
#define MUL2(d,a,b)   asm("mul.rn.f32x2 %0, %1, %2;"     : "=l"(d) : "l"(a), "l"(b))
#define PACK2(d,x)    asm("mov.b64 %0, {%1, %1};"        : "=l"(d) : "f"(x))
#define UNPACK2(lo,hi,p) asm("mov.b64 {%0, %1}, %2;" : "=f"(lo), "=f"(hi) : "l"(p))

// ---- scratch (device globals; no runtime allocation allowed) ----
__device__ float g_q[BH_*N_*HD_];      // 16 MB (normalized in-place)
__device__ float g_k[BH_*N_*HD_];      // 16 MB
__device__ float g_v[BH_*N_*HD_];      // 16 MB
__device__ float g_o[BH_*N_*HD_];      // 16 MB
__device__ float g_tab[TABN_*NH_];     // 127 KB
__device__ float g_biasT[NH_*N_*N_];   // 32 MB, layout [h][m][n]

// ============================================================
// K0: QKV projection with residual. x:(b,c,32,32) -> q,k,v [bh][n][d]
// ============================================================
__global__ void __launch_bounds__(256) qkv_kernel(
    const float* __restrict__ x,
    const float* __restrict__ q1w, const float* __restrict__ q1b,
    const float* __restrict__ q2w, const float* __restrict__ q2b,
    const float* __restrict__ k1w, const float* __restrict__ k1b,
    const float* __restrict__ k2w, const float* __restrict__ k2b,
    const float* __restrict__ v1w, const float* __restrict__ v1b,
    const float* __restrict__ v2w, const float* __restrict__ v2b)
{
    __shared__ float x_s[16][C_];      // 16 KB
    __shared__ float w_s[HALF_][32];   // 16 KB

    const int tid  = threadIdx.x;
    const int tok0 = blockIdx.x * 16;
    const int b    = tok0 / N_;
    const int n0   = tok0 % N_;

    for (int idx = tid; idx < 16 * C_; idx += 256) {
        int c = idx >> 4, t = idx & 15;
        x_s[t][c] = x[(b * C_ + c) * N_ + n0 + t];
    }
    __syncthreads();

    const float* Ws[6] = {q1w, q2w, k1w, k2w, v1w, v2w};
    const float* Bs[6] = {q1b, q2b, k1b, k2b, v1b, v2b};
    float*       Os[6] = {g_q, g_q, g_k, g_k, g_v, g_v};

    const int lane  = tid & 31;
    const int warp  = tid >> 5;
    const int t     = lane & 15;
    const int sub   = lane >> 4;
    const int oc0   = warp * 16 + sub * 8;

    for (int m = 0; m < 6; m++) {
        const int half = m & 1;
        const float* W  = Ws[m];
        const float* bb = Bs[m];

        float acc[8];
        #pragma unroll
        for (int u = 0; u < 8; u++)
            acc[u] = x_s[t][half * HALF_ + oc0 + u] + bb[oc0 + u];

        for (int ch = 0; ch < 4; ch++) {
            __syncthreads();
            for (int idx = tid; idx < HALF_ * 32; idx += 256) {
                int oc = idx >> 5, ii = idx & 31;
                w_s[oc][ii] = W[oc * HALF_ + ch * 32 + ii];
            }
            __syncthreads();
            #pragma unroll 8
            for (int ii = 0; ii < 32; ii++) {
                float xv = x_s[t][half * HALF_ + ch * 32 + ii];
                #pragma unroll
                for (int u = 0; u < 8; u++)
                    acc[u] += xv * w_s[oc0 + u][ii];
            }
        }

        const int c    = half * HALF_ + oc0;
        const int head = c >> 5, d = c & 31;
        float* out = Os[m] + (((b * NH_ + head) * N_) + (n0 + t)) * HD_ + d;
        *(float4*)(out)     = make_float4(acc[0], acc[1], acc[2], acc[3]);
        *(float4*)(out + 4) = make_float4(acc[4], acc[5], acc[6], acc[7]);
    }
}

// ============================================================
// K1: normalize q and k rows (length 32) in place.
// ============================================================
__global__ void __launch_bounds__(256) norm_kernel()
{
    int r = blockIdx.x * 256 + threadIdx.x;
    float* base = (r < BH_ * N_) ? g_q : g_k;
    int row = (r < BH_ * N_) ? r : r - BH_ * N_;
    float4* p = (float4*)(base + (size_t)row * HD_);
    float4 v[8];
    float s = 0.f;
    #pragma unroll
    for (int u = 0; u < 8; u++) {
        v[u] = p[u];
        s += v[u].x * v[u].x + v[u].y * v[u].y + v[u].z * v[u].z + v[u].w * v[u].w;
    }
    float inv = 1.f / fmaxf(sqrtf(s), 1e-12f);
    #pragma unroll
    for (int u = 0; u < 8; u++) {
        v[u].x *= inv; v[u].y *= inv; v[u].z *= inv; v[u].w *= inv;
        p[u] = v[u];
    }
}

// ============================================================
// K2: CPB table MLP
// ============================================================
__global__ void __launch_bounds__(256) tab_kernel(
    const float* __restrict__ w1, const float* __restrict__ b1,
    const float* __restrict__ w2)
{
    __shared__ float w1s[256];
    __shared__ float b1s[128];
    __shared__ float w2s[1024];
    int tid = threadIdx.x;
    if (tid < 256) w1s[tid] = w1[tid];
    if (tid < 128) b1s[tid] = b1[tid];
    for (int i = tid; i < 1024; i += 256) w2s[i] = w2[i];
    __syncthreads();

    int p = blockIdx.x * 256 + tid;
    if (p >= TABN_) return;
    int a = p / 63, b = p % 63;
    float t0 = ((float)(a - 31) / 31.0f) * 3.2f;
    float t1 = ((float)(b - 31) / 31.0f) * 3.2f;
    t0 = copysignf(1.f - __expf(-fabsf(t0)), t0);
    t1 = copysignf(1.f - __expf(-fabsf(t1)), t1);

    float acc[NH_];
    #pragma unroll
    for (int h = 0; h < NH_; h++) acc[h] = 0.f;
    for (int k = 0; k < 128; k++) {
        float hv = fmaxf(w1s[2 * k] * t0 + w1s[2 * k + 1] * t1 + b1s[k], 0.f);
        #pragma unroll
        for (int h = 0; h < NH_; h++) acc[h] += w2s[h * 128 + k] * hv;
    }
    #pragma unroll
    for (int h = 0; h < NH_; h++) g_tab[p * NH_ + h] = acc[h];
}

// ============================================================
// K3: expand bias to [h][m][n]
// ============================================================
__global__ void __launch_bounds__(256) bias_kernel()
{
    int m = blockIdx.x;
    int n = blockIdx.y * 256 + threadIdx.x;
    int i = n >> 5, j = n & 31;
    int p = m >> 5, q = m & 31;
    int idx = (i - p + 31) * 63 + (j - q + 31);
    const float* t = g_tab + idx * NH_;
    #pragma unroll
    for (int h = 0; h < NH_; h++) {
        float v = 16.f / (1.f + __expf(-t[h]));
        g_biasT[((size_t)h * N_ + m) * N_ + n] = v;
    }
}

// ============================================================
// K4: attention, fp32x2 packed math, 2 queries per thread.
// grid (N/256, BH), 128 threads. Streaming softmax with constant
// shift M = scale + 16 (exp arg in [-2*scale-16, 0]).
// launch_bounds(128,2): 255-reg budget -> NO spills (the round-2 fix).
// ============================================================
__global__ void __launch_bounds__(128, 2) attn_kernel(const float* __restrict__ logit_scale)
{
    const int MT = 32;                       // keys per tile
    __shared__ ulonglong2 k_s[MT * 8];       // 32 keys x 32 f32 = 4 KB
    __shared__ ulonglong2 v_s[MT * 8];       // 4 KB
    __shared__ float bias_s[MT][256];        // 32 KB

    const int tid = threadIdx.x;
    const int bh  = blockIdx.y;
    const int h   = bh & 7;
    const int q0  = blockIdx.x * 256 + tid * 2;   // two adjacent queries

    // q rows for both queries, packed as f32x2 (8 x ulonglong2 each)
    u64 qa[16], qb[16];
    {
        const ulonglong2* qpa = (const ulonglong2*)(g_q + ((size_t)bh * N_ + q0) * HD_);
        #pragma unroll
        for (int u = 0; u < 8; u++) {
            ulonglong2 t0 = qpa[u];     qa[2*u] = t0.x; qa[2*u+1] = t0.y;
            ulonglong2 t1 = qpa[u + 8]; qb[2*u] = t1.x; qb[2*u+1] = t1.y;
        }
    }

    const float scale = __expf(fminf(logit_scale[h], 4.6051702f)); // log(100)
    const float M = scale + 16.0f;

    u64 oa[16], ob[16];
    #pragma unroll
    for (int u = 0; u < 16; u++) { oa[u] = 0ull; ob[u] = 0ull; }
    float suma = 0.f, sumb = 0.f;

    const ulonglong2* kbase = (const ulonglong2*)(g_k + (size_t)bh * N_ * HD_);
    const ulonglong2* vbase = (const ulonglong2*)(g_v + (size_t)bh * N_ * HD_);
    const float*      bbase = g_biasT + (size_t)h * N_ * N_ + blockIdx.x * 256;

    for (int m0 = 0; m0 < N_; m0 += MT) {
        __syncthreads();
        // stage K/V tile: 32 keys x 8 ulonglong2 = 256 each, 128 threads -> 2 apiece
        #pragma unroll
        for (int u = 0; u < 2; u++) {
            k_s[u * 128 + tid] = kbase[m0 * 8 + u * 128 + tid];
            v_s[u * 128 + tid] = vbase[m0 * 8 + u * 128 + tid];
        }
        // stage bias tile [32 keys][256 queries] = 2048 float4
        #pragma unroll
        for (int u = 0; u < 16; u++) {
            int idx = u * 128 + tid;             // 0..2047
            int mm = idx >> 6, nn = idx & 63;
            ((float4*)bias_s)[idx] =
                *(const float4*)(bbase + (size_t)(m0 + mm) * N_ + nn * 4);
        }
        __syncthreads();

        #pragma unroll 2
        for (int j = 0; j < MT; j++) {
            // QK dots for both queries, 2 chains each for ILP
            u64 sa0 = 0ull, sa1 = 0ull, sb0 = 0ull, sb1 = 0ull;
            const ulonglong2* kk = &k_s[j * 8];
            #pragma unroll
            for (int u = 0; u < 4; u++) {
                ulonglong2 k0 = kk[2*u];
                ulonglong2 k1 = kk[2*u+1];
                FMA2(sa0, qa[4*u+0], k0.x, sa0);
                FMA2(sa1, qa[4*u+1], k0.y, sa1);
                FMA2(sb0, qb[4*u+0], k0.x, sb0);
                FMA2(sb1, qb[4*u+1], k0.y, sb1);
                FMA2(sa0, qa[4*u+2], k1.x, sa0);
                FMA2(sa1, qa[4*u+3], k1.y, sa1);
                FMA2(sb0, qb[4*u+2], k1.x, sb0);
                FMA2(sb1, qb[4*u+3], k1.y, sb1);
            }
            float a0l, a0h, a1l, a1h, b0l, b0h, b1l, b1h;
            UNPACK2(a0l, a0h, sa0); UNPACK2(a1l, a1h, sa1);
            UNPACK2(b0l, b0h, sb0); UNPACK2(b1l, b1h, sb1);
            float s_a = (a0l + a0h) + (a1l + a1h);
            float s_b = (b0l + b0h) + (b1l + b1h);

            float2 bij = *(const float2*)&bias_s[j][tid * 2];
            float pa = __expf(fmaf(s_a, scale, bij.x - M));
            float pb = __expf(fmaf(s_b, scale, bij.y - M));
            suma += pa; sumb += pb;

            u64 pa2, pb2;
            PACK2(pa2, pa); PACK2(pb2, pb);
            const ulonglong2* vv = &v_s[j * 8];
            #pragma unroll
            for (int u = 0; u < 8; u++) {
                ulonglong2 vj = vv[u];
                FMA2(oa[2*u],   pa2, vj.x, oa[2*u]);
                FMA2(oa[2*u+1], pa2, vj.y, oa[2*u+1]);
                FMA2(ob[2*u],   pb2, vj.x, ob[2*u]);
                FMA2(ob[2*u+1], pb2, vj.y, ob[2*u+1]);
            }
        }
    }

    float inva = 1.f / suma, invb = 1.f / sumb;
    u64 ia, ib; PACK2(ia, inva); PACK2(ib, invb);
    ulonglong2* op = (ulonglong2*)(g_o + ((size_t)bh * N_ + q0) * HD_);
    #pragma unroll
    for (int u = 0; u < 8; u++) {
        ulonglong2 ra, rb;
        MUL2(ra.x, oa[2*u], ia); MUL2(ra.y, oa[2*u+1], ia);
        MUL2(rb.x, ob[2*u], ib); MUL2(rb.y, ob[2*u+1], ib);
        op[u]     = ra;
        op[u + 8] = rb;
    }
}

// ============================================================
// K5: output projection, write NCHW output.
// ============================================================
__global__ void __launch_bounds__(256) proj_kernel(
    const float* __restrict__ p1w, const float* __restrict__ p1b,
    const float* __restrict__ p2w, const float* __restrict__ p2b,
    float* __restrict__ out)
{
    __shared__ float o_s[16][C_];
    __shared__ float w_s[HALF_][16];
    __shared__ float y_s[16][C_];

    const int tid  = threadIdx.x;
    const int tok0 = blockIdx.x * 16;
    const int b    = tok0 / N_;
    const int n0   = tok0 % N_;

    for (int idx = tid; idx < 16 * C_; idx += 256) {
        int t = idx >> 8, c = idx & 255;
        o_s[t][c] = g_o[(((size_t)b * NH_ + (c >> 5)) * N_ + n0 + t) * HD_ + (c & 31)];
    }
    __syncthreads();

    const float* Ws[2] = {p1w, p2w};
    const float* Bs[2] = {p1b, p2b};

    const int lane = tid & 31;
    const int warp = tid >> 5;
    const int t    = lane & 15;
    const int sub  = lane >> 4;
    const int oc0  = warp * 16 + sub * 8;

    for (int m = 0; m < 2; m++) {
        const int half = m;
        const float* W  = Ws[m];
        const float* bb = Bs[m];
        float acc[8];
        #pragma unroll
        for (int u = 0; u < 8; u++) acc[u] = bb[oc0 + u];

        for (int ch = 0; ch < 8; ch++) {
            __syncthreads();
            for (int idx = tid; idx < HALF_ * 16; idx += 256) {
                int oc = idx >> 4, ii = idx & 15;
                w_s[oc][ii] = W[oc * HALF_ + ch * 16 + ii];
            }
            __syncthreads();
            #pragma unroll 8
            for (int ii = 0; ii < 16; ii++) {
                float xv = o_s[t][half * HALF_ + ch * 16 + ii];
                #pragma unroll
                for (int u = 0; u < 8; u++)
                    acc[u] += xv * w_s[oc0 + u][ii];
            }
        }
        #pragma unroll
        for (int u = 0; u < 8; u++) y_s[t][half * HALF_ + oc0 + u] = acc[u];
    }
    __syncthreads();

    for (int idx = tid; idx < 16 * C_; idx += 256) {
        int c = idx >> 4, t2 = idx & 15;
        out[((size_t)b * C_ + c) * N_ + n0 + t2] = y_s[t2][c];
    }
}

// ============================================================
extern "C" void kernel_launch(void* const* d_in, const int* in_sizes, int n_in,
                              void* d_out, int out_size)
{
    const float* x    = (const float*)d_in[0];
    const float* q1w  = (const float*)d_in[1];
    const float* q1b  = (const float*)d_in[2];
    const float* q2w  = (const float*)d_in[3];
    const float* q2b  = (const float*)d_in[4];
    const float* k1w  = (const float*)d_in[5];
    const float* k1b  = (const float*)d_in[6];
    const float* k2w  = (const float*)d_in[7];
    const float* k2b  = (const float*)d_in[8];
    const float* v1w  = (const float*)d_in[9];
    const float* v1b  = (const float*)d_in[10];
    const float* v2w  = (const float*)d_in[11];
    const float* v2b  = (const float*)d_in[12];
    const float* p1w  = (const float*)d_in[13];
    const float* p1b  = (const float*)d_in[14];
    const float* p2w  = (const float*)d_in[15];
    const float* p2b  = (const float*)d_in[16];
    const float* ls   = (const float*)d_in[17];
    const float* m1w  = (const float*)d_in[18];
    const float* m1b  = (const float*)d_in[19];
    const float* m2w  = (const float*)d_in[20];
    float* out = (float*)d_out;

    qkv_kernel<<<B_ * N_ / 16, 256>>>(x, q1w, q1b, q2w, q2b,
                                      k1w, k1b, k2w, k2b,
                                      v1w, v1b, v2w, v2b);
    norm_kernel<<<2 * BH_ * N_ / 256, 256>>>();
    tab_kernel<<<(TABN_ + 255) / 256, 256>>>(m1w, m1b, m2w);
    bias_kernel<<<dim3(N_, N_ / 256), 256>>>();
    attn_kernel<<<dim3(N_ / 256, BH_), 128>>>(ls);
    proj_kernel<<<B_ * N_ / 16, 256>>>(p1w, p1b, p2w, p2b, out);
}

// round 4
// speedup vs baseline: 1.2035x; 1.0393x over previous
#include <cuda_runtime.h>
#include <math.h>
#include <stdint.h>

#define B_    16
#define C_    256
#define N_    1024      // 32*32 tokens
#define NH_   8
#define HD_   32
#define HALF_ 128
#define BH_   (B_*NH_)  // 128
#define TABN_ 3969      // 63*63

typedef unsigned long long u64;

// packed fp32x2 ops (sm_100+; ptxas never auto-generates these)
#define FMA2(d,a,b,c) asm("fma.rn.f32x2 %0, %1, %2, %3;" : "=l"(d) : "l"(a), "l"(b), "l"(c))
#define MUL2(d,a,b)   asm("mul.rn.f32x2 %0, %1, %2;"     : "=l"(d) : "l"(a), "l"(b))
#define PACK2(d,x)    asm("mov.b64 %0, {%1, %1};"        : "=l"(d) : "f"(x))
#define UNPACK2(lo,hi,p) asm("mov.b64 {%0, %1}, %2;" : "=f"(lo), "=f"(hi) : "l"(p))

// ---- scratch (device globals; no runtime allocation allowed) ----
__device__ float g_q[BH_*N_*HD_];      // 16 MB (stored normalized)
__device__ float g_k[BH_*N_*HD_];      // 16 MB (stored normalized)
__device__ float g_v[BH_*N_*HD_];      // 16 MB
__device__ float g_o[BH_*N_*HD_];      // 16 MB
__device__ float g_tab[TABN_*NH_];     // 127 KB
__device__ float g_biasT[NH_*N_*N_];   // 32 MB, layout [h][m][n]

// ============================================================
// K2: CPB table MLP (launched FIRST)
// ============================================================
__global__ void __launch_bounds__(256) tab_kernel(
    const float* __restrict__ w1, const float* __restrict__ b1,
    const float* __restrict__ w2)
{
    __shared__ float w1s[256];
    __shared__ float b1s[128];
    __shared__ float w2s[1024];
    int tid = threadIdx.x;
    if (tid < 256) w1s[tid] = w1[tid];
    if (tid < 128) b1s[tid] = b1[tid];
    for (int i = tid; i < 1024; i += 256) w2s[i] = w2[i];
    __syncthreads();

    int p = blockIdx.x * 256 + tid;
    if (p >= TABN_) return;
    int a = p / 63, b = p % 63;
    float t0 = ((float)(a - 31) / 31.0f) * 3.2f;
    float t1 = ((float)(b - 31) / 31.0f) * 3.2f;
    t0 = copysignf(1.f - __expf(-fabsf(t0)), t0);
    t1 = copysignf(1.f - __expf(-fabsf(t1)), t1);

    float acc[NH_];
    #pragma unroll
    for (int h = 0; h < NH_; h++) acc[h] = 0.f;
    for (int k = 0; k < 128; k++) {
        float hv = fmaxf(w1s[2 * k] * t0 + w1s[2 * k + 1] * t1 + b1s[k], 0.f);
        #pragma unroll
        for (int h = 0; h < NH_; h++) acc[h] += w2s[h * 128 + k] * hv;
    }
    #pragma unroll
    for (int h = 0; h < NH_; h++) g_tab[p * NH_ + h] = acc[h];
}

// ============================================================
// K3: expand bias to [h][m][n]
// ============================================================
__global__ void __launch_bounds__(256) bias_kernel()
{
    int m = blockIdx.x;
    int n = blockIdx.y * 256 + threadIdx.x;
    int i = n >> 5, j = n & 31;
    int p = m >> 5, q = m & 31;
    int idx = (i - p + 31) * 63 + (j - q + 31);
    const float* t = g_tab + idx * NH_;
    #pragma unroll
    for (int h = 0; h < NH_; h++) {
        float v = 16.f / (1.f + __expf(-t[h]));
        g_biasT[((size_t)h * N_ + m) * N_ + n] = v;
    }
}

// ============================================================
// K0: QKV projection with residual + FUSED q/k normalization.
// Each block computes the complete q,k,v for its 16 tokens, so q/k
// rows can be normalized in smem before the global store.
// ============================================================
__global__ void __launch_bounds__(256) qkv_kernel(
    const float* __restrict__ x,
    const float* __restrict__ q1w, const float* __restrict__ q1b,
    const float* __restrict__ q2w, const float* __restrict__ q2b,
    const float* __restrict__ k1w, const float* __restrict__ k1b,
    const float* __restrict__ k2w, const float* __restrict__ k2b,
    const float* __restrict__ v1w, const float* __restrict__ v1b,
    const float* __restrict__ v2w, const float* __restrict__ v2b)
{
    __shared__ float x_s[16][C_];       // 16 KB
    __shared__ float w_s[HALF_][32];    // 16 KB
    __shared__ float buf_s[16][264];    // 16.9 KB (padded: bank-friendly row reads)

    const int tid  = threadIdx.x;
    const int tok0 = blockIdx.x * 16;
    const int b    = tok0 / N_;
    const int n0   = tok0 % N_;

    for (int idx = tid; idx < 16 * C_; idx += 256) {
        int c = idx >> 4, t = idx & 15;
        x_s[t][c] = x[(b * C_ + c) * N_ + n0 + t];
    }
    __syncthreads();

    const float* Ws[6] = {q1w, q2w, k1w, k2w, v1w, v2w};
    const float* Bs[6] = {q1b, q2b, k1b, k2b, v1b, v2b};

    const int lane  = tid & 31;
    const int warp  = tid >> 5;
    const int t     = lane & 15;
    const int sub   = lane >> 4;
    const int oc0   = warp * 16 + sub * 8;

    for (int pair = 0; pair < 3; pair++) {
        for (int half = 0; half < 2; half++) {
            const int m = pair * 2 + half;
            const float* W  = Ws[m];
            const float* bb = Bs[m];

            float acc[8];
            #pragma unroll
            for (int u = 0; u < 8; u++)
                acc[u] = x_s[t][half * HALF_ + oc0 + u] + bb[oc0 + u];

            for (int ch = 0; ch < 4; ch++) {
                __syncthreads();
                for (int idx = tid; idx < HALF_ * 32; idx += 256) {
                    int oc = idx >> 5, ii = idx & 31;
                    w_s[oc][ii] = W[oc * HALF_ + ch * 32 + ii];
                }
                __syncthreads();
                #pragma unroll 8
                for (int ii = 0; ii < 32; ii++) {
                    float xv = x_s[t][half * HALF_ + ch * 32 + ii];
                    #pragma unroll
                    for (int u = 0; u < 8; u++)
                        acc[u] += xv * w_s[oc0 + u][ii];
                }
            }

            if (pair < 2) {
                // q or k: park in smem for normalization
                #pragma unroll
                for (int u = 0; u < 8; u++)
                    buf_s[t][half * HALF_ + oc0 + u] = acc[u];
            } else {
                // v: store directly
                const int c    = half * HALF_ + oc0;
                const int head = c >> 5, d = c & 31;
                float* out = g_v + (((b * NH_ + head) * N_) + (n0 + t)) * HD_ + d;
                *(float4*)(out)     = make_float4(acc[0], acc[1], acc[2], acc[3]);
                *(float4*)(out + 4) = make_float4(acc[4], acc[5], acc[6], acc[7]);
            }
        }

        if (pair < 2) {
            __syncthreads();
            if (tid < 128) {
                const int t2   = tid >> 3;
                const int head = tid & 7;
                float4 r[8];
                float s = 0.f;
                #pragma unroll
                for (int i = 0; i < 8; i++) {
                    r[i] = *(float4*)&buf_s[t2][head * 32 + i * 4];
                    s += r[i].x * r[i].x + r[i].y * r[i].y
                       + r[i].z * r[i].z + r[i].w * r[i].w;
                }
                float inv = 1.f / fmaxf(sqrtf(s), 1e-12f);
                float* dst = (pair == 0 ? g_q : g_k)
                           + (((b * NH_ + head) * N_) + (n0 + t2)) * HD_;
                #pragma unroll
                for (int i = 0; i < 8; i++) {
                    r[i].x *= inv; r[i].y *= inv; r[i].z *= inv; r[i].w *= inv;
                    *(float4*)(dst + i * 4) = r[i];
                }
            }
            __syncthreads();
        }
    }
}

// ============================================================
// K4: attention. 2 queries/thread, f32x2 math, bias via prefetched
// LDG (no smem bias tile). Streaming softmax with constant shift.
// ============================================================
__global__ void __launch_bounds__(128, 2) attn_kernel(const float* __restrict__ logit_scale)
{
    const int MT = 32;                       // keys per tile
    __shared__ ulonglong2 k_s[MT * 8];       // 4 KB
    __shared__ ulonglong2 v_s[MT * 8];       // 4 KB

    const int tid = threadIdx.x;
    const int bh  = blockIdx.y;
    const int h   = bh & 7;
    const int q0  = blockIdx.x * 256 + tid * 2;

    u64 qa[16], qb[16];
    {
        const ulonglong2* qpa = (const ulonglong2*)(g_q + ((size_t)bh * N_ + q0) * HD_);
        #pragma unroll
        for (int u = 0; u < 8; u++) {
            ulonglong2 t0 = qpa[u];     qa[2*u] = t0.x; qa[2*u+1] = t0.y;
            ulonglong2 t1 = qpa[u + 8]; qb[2*u] = t1.x; qb[2*u+1] = t1.y;
        }
    }

    const float scale = __expf(fminf(logit_scale[h], 4.6051702f)); // log(100)
    const float M = scale + 16.0f;

    u64 oa[16], ob[16];
    #pragma unroll
    for (int u = 0; u < 16; u++) { oa[u] = 0ull; ob[u] = 0ull; }
    float suma = 0.f, sumb = 0.f;

    const ulonglong2* kbase = (const ulonglong2*)(g_k + (size_t)bh * N_ * HD_);
    const ulonglong2* vbase = (const ulonglong2*)(g_v + (size_t)bh * N_ * HD_);
    const float*      bbase = g_biasT + (size_t)h * N_ * N_ + blockIdx.x * 256;

    // bias prefetch ring: 4 keys ahead (covers L2 latency)
    float2 bpre[4];
    #pragma unroll
    for (int i = 0; i < 4; i++)
        bpre[i] = __ldg((const float2*)(bbase + (size_t)i * N_) + tid);

    for (int m0 = 0; m0 < N_; m0 += MT) {
        __syncthreads();
        #pragma unroll
        for (int u = 0; u < 2; u++) {
            k_s[u * 128 + tid] = kbase[m0 * 8 + u * 128 + tid];
            v_s[u * 128 + tid] = vbase[m0 * 8 + u * 128 + tid];
        }
        __syncthreads();

        #pragma unroll 4
        for (int j = 0; j < MT; j++) {
            float2 bij = bpre[j & 3];
            int nr = m0 + j + 4;
            if (nr < N_)
                bpre[j & 3] = __ldg((const float2*)(bbase + (size_t)nr * N_) + tid);

            u64 sa0 = 0ull, sa1 = 0ull, sb0 = 0ull, sb1 = 0ull;
            const ulonglong2* kk = &k_s[j * 8];
            #pragma unroll
            for (int u = 0; u < 4; u++) {
                ulonglong2 k0 = kk[2*u];
                ulonglong2 k1 = kk[2*u+1];
                FMA2(sa0, qa[4*u+0], k0.x, sa0);
                FMA2(sa1, qa[4*u+1], k0.y, sa1);
                FMA2(sb0, qb[4*u+0], k0.x, sb0);
                FMA2(sb1, qb[4*u+1], k0.y, sb1);
                FMA2(sa0, qa[4*u+2], k1.x, sa0);
                FMA2(sa1, qa[4*u+3], k1.y, sa1);
                FMA2(sb0, qb[4*u+2], k1.x, sb0);
                FMA2(sb1, qb[4*u+3], k1.y, sb1);
            }
            float a0l, a0h, a1l, a1h, b0l, b0h, b1l, b1h;
            UNPACK2(a0l, a0h, sa0); UNPACK2(a1l, a1h, sa1);
            UNPACK2(b0l, b0h, sb0); UNPACK2(b1l, b1h, sb1);
            float s_a = (a0l + a0h) + (a1l + a1h);
            float s_b = (b0l + b0h) + (b1l + b1h);

            float pa = __expf(fmaf(s_a, scale, bij.x - M));
            float pb = __expf(fmaf(s_b, scale, bij.y - M));
            suma += pa; sumb += pb;

            u64 pa2, pb2;
            PACK2(pa2, pa); PACK2(pb2, pb);
            const ulonglong2* vv = &v_s[j * 8];
            #pragma unroll
            for (int u = 0; u < 8; u++) {
                ulonglong2 vj = vv[u];
                FMA2(oa[2*u],   pa2, vj.x, oa[2*u]);
                FMA2(oa[2*u+1], pa2, vj.y, oa[2*u+1]);
                FMA2(ob[2*u],   pb2, vj.x, ob[2*u]);
                FMA2(ob[2*u+1], pb2, vj.y, ob[2*u+1]);
            }
        }
    }

    float inva = 1.f / suma, invb = 1.f / sumb;
    u64 ia, ib; PACK2(ia, inva); PACK2(ib, invb);
    ulonglong2* op = (ulonglong2*)(g_o + ((size_t)bh * N_ + q0) * HD_);
    #pragma unroll
    for (int u = 0; u < 8; u++) {
        ulonglong2 ra, rb;
        MUL2(ra.x, oa[2*u], ia); MUL2(ra.y, oa[2*u+1], ia);
        MUL2(rb.x, ob[2*u], ib); MUL2(rb.y, ob[2*u+1], ib);
        op[u]     = ra;
        op[u + 8] = rb;
    }
}

// ============================================================
// K5: output projection, write NCHW output.
// ============================================================
__global__ void __launch_bounds__(256) proj_kernel(
    const float* __restrict__ p1w, const float* __restrict__ p1b,
    const float* __restrict__ p2w, const float* __restrict__ p2b,
    float* __restrict__ out)
{
    __shared__ float o_s[16][C_];
    __shared__ float w_s[HALF_][16];
    __shared__ float y_s[16][C_];

    const int tid  = threadIdx.x;
    const int tok0 = blockIdx.x * 16;
    const int b    = tok0 / N_;
    const int n0   = tok0 % N_;

    for (int idx = tid; idx < 16 * C_; idx += 256) {
        int t = idx >> 8, c = idx & 255;
        o_s[t][c] = g_o[(((size_t)b * NH_ + (c >> 5)) * N_ + n0 + t) * HD_ + (c & 31)];
    }
    __syncthreads();

    const float* Ws[2] = {p1w, p2w};
    const float* Bs[2] = {p1b, p2b};

    const int lane = tid & 31;
    const int warp = tid >> 5;
    const int t    = lane & 15;
    const int sub  = lane >> 4;
    const int oc0  = warp * 16 + sub * 8;

    for (int m = 0; m < 2; m++) {
        const int half = m;
        const float* W  = Ws[m];
        const float* bb = Bs[m];
        float acc[8];
        #pragma unroll
        for (int u = 0; u < 8; u++) acc[u] = bb[oc0 + u];

        for (int ch = 0; ch < 8; ch++) {
            __syncthreads();
            for (int idx = tid; idx < HALF_ * 16; idx += 256) {
                int oc = idx >> 4, ii = idx & 15;
                w_s[oc][ii] = W[oc * HALF_ + ch * 16 + ii];
            }
            __syncthreads();
            #pragma unroll 8
            for (int ii = 0; ii < 16; ii++) {
                float xv = o_s[t][half * HALF_ + ch * 16 + ii];
                #pragma unroll
                for (int u = 0; u < 8; u++)
                    acc[u] += xv * w_s[oc0 + u][ii];
            }
        }
        #pragma unroll
        for (int u = 0; u < 8; u++) y_s[t][half * HALF_ + oc0 + u] = acc[u];
    }
    __syncthreads();

    for (int idx = tid; idx < 16 * C_; idx += 256) {
        int c = idx >> 4, t2 = idx & 15;
        out[((size_t)b * C_ + c) * N_ + n0 + t2] = y_s[t2][c];
    }
}

// ============================================================
extern "C" void kernel_launch(void* const* d_in, const int* in_sizes, int n_in,
                              void* d_out, int out_size)
{
    const float* x    = (const float*)d_in[0];
    const float* q1w  = (const float*)d_in[1];
    const float* q1b  = (const float*)d_in[2];
    const float* q2w  = (const float*)d_in[3];
    const float* q2b  = (const float*)d_in[4];
    const float* k1w  = (const float*)d_in[5];
    const float* k1b  = (const float*)d_in[6];
    const float* k2w  = (const float*)d_in[7];
    const float* k2b  = (const float*)d_in[8];
    const float* v1w  = (const float*)d_in[9];
    const float* v1b  = (const float*)d_in[10];
    const float* v2w  = (const float*)d_in[11];
    const float* v2b  = (const float*)d_in[12];
    const float* p1w  = (const float*)d_in[13];
    const float* p1b  = (const float*)d_in[14];
    const float* p2w  = (const float*)d_in[15];
    const float* p2b  = (const float*)d_in[16];
    const float* ls   = (const float*)d_in[17];
    const float* m1w  = (const float*)d_in[18];
    const float* m1b  = (const float*)d_in[19];
    const float* m2w  = (const float*)d_in[20];
    float* out = (float*)d_out;

    // Order chosen so attn_kernel is app-launch index 3 (the ncu slot).
    tab_kernel<<<(TABN_ + 255) / 256, 256>>>(m1w, m1b, m2w);
    bias_kernel<<<dim3(N_, N_ / 256), 256>>>();
    qkv_kernel<<<B_ * N_ / 16, 256>>>(x, q1w, q1b, q2w, q2b,
                                      k1w, k1b, k2w, k2b,
                                      v1w, v1b, v2w, v2b);
    attn_kernel<<<dim3(N_ / 256, BH_), 128>>>(ls);
    proj_kernel<<<B_ * N_ / 16, 256>>>(p1w, p1b, p2w, p2b, out);
}